// round 10
// baseline (speedup 1.0000x reference)
#include <cuda_runtime.h>

// ---------------- scratch (__device__ globals; no allocation allowed) ----------------
__device__ float g_hx[8*32*256];
__device__ float g_hy[8*32*256];
__device__ float g_hz[8*32*256];
__device__ float g_partmax[8*2*32];          // per (b,h,x) block max
__device__ float g_partsum[8*2*32];          // per (b,h,x) Σexp(v - localmax)
__device__ float g_part[8*32*256];           // per (b,x) logits partials
__device__ unsigned g_cntB[8];               // per-b arrivals for softmax stats
__device__ unsigned g_cntAll;                // arrivals for g_part completion

// ---------------- K1: projections  h = relu(in @ (g/||V||*V)^T + b) ----------------
// grid (4 k-quads, 8 b, 3 mats), 256 threads. Also resets the sync counters.
__global__ void __launch_bounds__(256) k_proj(
    const float* __restrict__ xin, const float* __restrict__ yin, const float* __restrict__ zin,
    const float* __restrict__ Vx, const float* __restrict__ gx, const float* __restrict__ bx,
    const float* __restrict__ Vy, const float* __restrict__ gy, const float* __restrict__ by,
    const float* __restrict__ Vz, const float* __restrict__ gz, const float* __restrict__ bz) {
    __shared__ float sIn[32*128];
    __shared__ float sV[64*33];
    __shared__ float red[256];
    int q = blockIdx.x, b = blockIdx.y, m = blockIdx.z;
    int tid = threadIdx.x;
    if (q == 0 && b == 0 && m == 0) {               // counter reset (stream-ordered)
        if (tid < 8) g_cntB[tid] = 0;
        if (tid == 8) g_cntAll = 0;
    }
    const float* in   = (m == 0) ? xin : (m == 1) ? yin : zin;
    const float* V    = (m == 0) ? Vx  : (m == 1) ? Vy  : Vz;
    const float* gp   = (m == 0) ? gx  : (m == 1) ? gy  : gz;
    const float* bias = (m == 0) ? bx  : (m == 1) ? by  : bz;
    float* out        = (m == 0) ? g_hx : (m == 1) ? g_hy : g_hz;
    int k0 = q * 64;

    for (int e = tid; e < 4096; e += 256) sIn[e] = in[b * 4096 + e];
    float ss = 0.f;
    for (int i = tid; i < 32768; i += 256) { float v = V[i]; ss += v * v; }
    red[tid] = ss; __syncthreads();
    for (int s = 128; s > 0; s >>= 1) {
        if (tid < s) red[tid] += red[tid + s];
        __syncthreads();
    }
    float scale = gp[0] / sqrtf(red[0]);

    int kk = tid & 63, rg = tid >> 6, r0 = rg * 8;
    float acc[8] = {0,0,0,0,0,0,0,0};
    for (int dc = 0; dc < 128; dc += 32) {
        __syncthreads();
        for (int e = tid; e < 2048; e += 256) {
            int kr = e >> 5, d = e & 31;
            sV[kr * 33 + d] = V[(k0 + kr) * 128 + dc + d];
        }
        __syncthreads();
        for (int d = 0; d < 32; d += 4) {
            float v0 = sV[kk*33 + d],     v1 = sV[kk*33 + d + 1];
            float v2 = sV[kk*33 + d + 2], v3 = sV[kk*33 + d + 3];
            #pragma unroll
            for (int r = 0; r < 8; r++) {
                float4 iv = *(const float4*)&sIn[(r0 + r) * 128 + dc + d];
                acc[r] += iv.x * v0 + iv.y * v1 + iv.z * v2 + iv.w * v3;
            }
        }
    }
    float bb = bias[k0 + kk];
    #pragma unroll
    for (int r = 0; r < 8; r++) {
        float v = acc[r] * scale + bb;
        out[(b * 32 + r0 + r) * 256 + k0 + kk] = v > 0.f ? v : 0.f;
    }
}

// ---------------- shared memory union for k_attfuse ----------------
union SMem2 {
    struct { float st[32*64]; float sw[64*68]; float red[128]; } att;      // ~26 KB
    struct { float shz[256*36]; float sa[1024]; float sstat[4]; } fuse;    // ~41 KB
};

// ---------------- K2: att GEMM + softmax + att_out + logit partials + BN ----------------
// grid 256 x 128 threads; 41KB smem -> 5 blocks/SM possible, need only 2 -> co-residency
// guaranteed with >2x margin. Per-b stats barrier among 32 blocks; LAST arriving block
// (atomicAdd ticket == 255) runs the BatchNorm epilogue itself (no extra blocks, no
// grid-wide spin).
__global__ void __launch_bounds__(128) k_attfuse(
    const float* __restrict__ Vh, const float* __restrict__ ghp, const float* __restrict__ bhp,
    const float* __restrict__ gamma, const float* __restrict__ beta,
    float* __restrict__ outp, float* __restrict__ att_out) {
    __shared__ SMem2 sm;
    __shared__ unsigned s_last;
    int tid = threadIdx.x;
    int blk = blockIdx.x;

    int x = blk & 31, b = blk >> 5;
    int yg = tid >> 4, zg = tid & 15;

    // ||Vh||
    float ssh = 0.f;
    for (int i = tid; i < 512; i += 128) { float v = Vh[i]; ssh += v * v; }
    sm.att.red[tid] = ssh; __syncthreads();
    for (int s = 64; s > 0; s >>= 1) { if (tid < s) sm.att.red[tid] += sm.att.red[tid + s]; __syncthreads(); }
    float scaleH = ghp[0] / sqrtf(sm.att.red[0]);
    float b0 = bhp[0], b1 = bhp[1];

    // GEMM: 4y x 4zh register tile
    float4 acc[4];
    acc[0] = acc[1] = acc[2] = acc[3] = make_float4(0.f, 0.f, 0.f, 0.f);
    const float* hx  = g_hx + (b * 32 + x) * 256;
    const float* hyB = g_hy + b * 8192;
    const float* hzB = g_hz + b * 8192;
    for (int c = 0; c < 4; c++) {
        int k0 = c * 64;
        __syncthreads();
        for (int e = tid; e < 2048; e += 128) {
            int kc = e & 63, y = e >> 6;
            sm.att.st[y * 64 + kc] = hx[k0 + kc] * hyB[y * 256 + k0 + kc];
        }
        for (int e = tid; e < 4096; e += 128) {
            int kc = e & 63, zh = e >> 6;
            sm.att.sw[kc * 68 + zh] = hzB[(zh >> 1) * 256 + k0 + kc] *
                                      Vh[(zh & 1) * 256 + k0 + kc] * scaleH;
        }
        __syncthreads();
        #pragma unroll 4
        for (int kc = 0; kc < 64; kc++) {
            float4 w = *(const float4*)&sm.att.sw[kc * 68 + zg * 4];
            float t0 = sm.att.st[(yg*4 + 0) * 64 + kc];
            float t1 = sm.att.st[(yg*4 + 1) * 64 + kc];
            float t2 = sm.att.st[(yg*4 + 2) * 64 + kc];
            float t3 = sm.att.st[(yg*4 + 3) * 64 + kc];
            acc[0].x += t0*w.x; acc[0].y += t0*w.y; acc[0].z += t0*w.z; acc[0].w += t0*w.w;
            acc[1].x += t1*w.x; acc[1].y += t1*w.y; acc[1].z += t1*w.z; acc[1].w += t1*w.w;
            acc[2].x += t2*w.x; acc[2].y += t2*w.y; acc[2].z += t2*w.z; acc[2].w += t2*w.w;
            acc[3].x += t3*w.x; acc[3].y += t3*w.y; acc[3].z += t3*w.z; acc[3].w += t3*w.w;
        }
    }
    // add bias into accumulators; local max
    float m0 = -1e30f, m1 = -1e30f;
    #pragma unroll
    for (int i = 0; i < 4; i++) {
        acc[i].x += b0; acc[i].y += b1; acc[i].z += b0; acc[i].w += b1;
        m0 = fmaxf(m0, fmaxf(acc[i].x, acc[i].z));
        m1 = fmaxf(m1, fmaxf(acc[i].y, acc[i].w));
    }
    __syncthreads();
    sm.att.red[tid] = m0; __syncthreads();
    for (int s = 64; s > 0; s >>= 1) { if (tid < s) sm.att.red[tid] = fmaxf(sm.att.red[tid], sm.att.red[tid + s]); __syncthreads(); }
    float M0l = sm.att.red[0]; __syncthreads();
    sm.att.red[tid] = m1; __syncthreads();
    for (int s = 64; s > 0; s >>= 1) { if (tid < s) sm.att.red[tid] = fmaxf(sm.att.red[tid], sm.att.red[tid + s]); __syncthreads(); }
    float M1l = sm.att.red[0]; __syncthreads();
    float s0 = 0.f, s1 = 0.f;
    #pragma unroll
    for (int i = 0; i < 4; i++) {
        s0 += expf(acc[i].x - M0l) + expf(acc[i].z - M0l);
        s1 += expf(acc[i].y - M1l) + expf(acc[i].w - M1l);
    }
    sm.att.red[tid] = s0; __syncthreads();
    for (int s = 64; s > 0; s >>= 1) { if (tid < s) sm.att.red[tid] += sm.att.red[tid + s]; __syncthreads(); }
    float S0l = sm.att.red[0]; __syncthreads();
    sm.att.red[tid] = s1; __syncthreads();
    for (int s = 64; s > 0; s >>= 1) { if (tid < s) sm.att.red[tid] += sm.att.red[tid + s]; __syncthreads(); }
    float S1l = sm.att.red[0];
    if (tid == 0) {
        g_partmax[(b * 2 + 0) * 32 + x] = M0l;
        g_partmax[(b * 2 + 1) * 32 + x] = M1l;
        g_partsum[(b * 2 + 0) * 32 + x] = S0l;
        g_partsum[(b * 2 + 1) * 32 + x] = S1l;
        __threadfence();
        atomicAdd(&g_cntB[b], 1u);
        // wait for the 32 sibling blocks of this b (co-residency guaranteed: 256 blocks,
        // 2/SM needed vs 5/SM possible)
        while (*(volatile unsigned*)&g_cntB[b] < 32u) { __nanosleep(64); }
    }
    __syncthreads();

    // combine 32 online-softmax partials per head (warps 0,1)
    if (tid < 64) {
        int h = tid >> 5, lane = tid & 31;
        float m = __ldcg(&g_partmax[(b * 2 + h) * 32 + lane]);
        float s = __ldcg(&g_partsum[(b * 2 + h) * 32 + lane]);
        float M = m;
        #pragma unroll
        for (int o = 16; o > 0; o >>= 1) M = fmaxf(M, __shfl_xor_sync(0xffffffffu, M, o));
        float se = s * expf(m - M);
        #pragma unroll
        for (int o = 16; o > 0; o >>= 1) se += __shfl_xor_sync(0xffffffffu, se, o);
        if (lane == 0) { sm.fuse.sstat[h * 2] = M; sm.fuse.sstat[h * 2 + 1] = 1.f / se; }
    }
    __syncthreads();
    float M0 = sm.fuse.sstat[0], I0 = sm.fuse.sstat[1];
    float M1 = sm.fuse.sstat[2], I1 = sm.fuse.sstat[3];

    // exp straight from registers -> att_out + sa (no g_attraw round-trip)
    float* o0 = att_out + ((b * 2 + 0) * 32 + x) * 1024;
    float* o1 = att_out + ((b * 2 + 1) * 32 + x) * 1024;
    int z0 = zg * 2;
    #pragma unroll
    for (int i = 0; i < 4; i++) {
        int y = yg * 4 + i;
        float a00 = expf(acc[i].x - M0) * I0;   // (h0, z0)
        float a10 = expf(acc[i].y - M1) * I1;   // (h1, z0)
        float a01 = expf(acc[i].z - M0) * I0;   // (h0, z0+1)
        float a11 = expf(acc[i].w - M1) * I1;   // (h1, z0+1)
        o0[y * 32 + z0]     = a00;
        o1[y * 32 + z0]     = a10;
        o0[y * 32 + z0 + 1] = a01;
        o1[y * 32 + z0 + 1] = a11;
        sm.fuse.sa[y * 32 + z0]     = a00 + a10;
        sm.fuse.sa[y * 32 + z0 + 1] = a01 + a11;
    }
    // stage hz transposed [k][z]
    for (int e = tid; e < 8192; e += 128) {
        int k = e & 255, z = e >> 8;
        sm.fuse.shz[k * 36 + z] = hzB[z * 256 + k];
    }
    __syncthreads();

    // logit partials: 128 threads, 2 k's each
    #pragma unroll
    for (int j = 0; j < 2; j++) {
        int kk = tid + j * 128;
        float sxk = hx[kk];
        float accl = 0.f;
        for (int y = 0; y < 32; y++) {
            float s = 0.f;
            #pragma unroll
            for (int z = 0; z < 32; z += 4) {
                float4 a4 = *(const float4*)&sm.fuse.sa[y * 32 + z];
                float4 h4 = *(const float4*)&sm.fuse.shz[kk * 36 + z];
                s += a4.x*h4.x + a4.y*h4.y + a4.z*h4.z + a4.w*h4.w;
            }
            accl += sxk * hyB[y * 256 + kk] * s;
        }
        g_part[(b * 32 + x) * 256 + kk] = accl;
    }
    __syncthreads();

    // ---- last-arriving block performs the BatchNorm epilogue ----
    if (tid == 0) {
        __threadfence();
        s_last = atomicAdd(&g_cntAll, 1u);    // ticket; 255 => last
    }
    __syncthreads();
    if (s_last == 255u) {
        // each thread handles 2 k-columns; reduce over x per batch, then normalize
        #pragma unroll
        for (int j = 0; j < 2; j++) {
            int k = tid + j * 128;
            float l[8];
            #pragma unroll
            for (int bb = 0; bb < 8; bb++) {
                float s = 0.f;
                #pragma unroll 8
                for (int xx = 0; xx < 32; xx++) s += __ldcg(&g_part[(bb * 32 + xx) * 256 + k]);
                l[bb] = s;
            }
            float mean = 0.f;
            #pragma unroll
            for (int bb = 0; bb < 8; bb++) mean += l[bb];
            mean *= 0.125f;
            float var = 0.f;
            #pragma unroll
            for (int bb = 0; bb < 8; bb++) { float d = l[bb] - mean; var += d * d; }
            var *= 0.125f;
            float sc = gamma[k] / sqrtf(var + 1e-5f);
            float bt = beta[k];
            #pragma unroll
            for (int bb = 0; bb < 8; bb++) outp[bb * 256 + k] = (l[bb] - mean) * sc + bt;
        }
    }
}

// ---------------- launch ----------------
extern "C" void kernel_launch(void* const* d_in, const int* in_sizes, int n_in,
                              void* d_out, int out_size) {
    const float* x     = (const float*)d_in[0];
    const float* y     = (const float*)d_in[1];
    const float* z     = (const float*)d_in[2];
    const float* Vx    = (const float*)d_in[3];
    const float* gx    = (const float*)d_in[4];
    const float* bx    = (const float*)d_in[5];
    const float* Vy    = (const float*)d_in[6];
    const float* gy    = (const float*)d_in[7];
    const float* by    = (const float*)d_in[8];
    const float* Vz    = (const float*)d_in[9];
    const float* gz    = (const float*)d_in[10];
    const float* bz    = (const float*)d_in[11];
    const float* Vh    = (const float*)d_in[12];
    const float* gh    = (const float*)d_in[13];
    const float* bh    = (const float*)d_in[14];
    const float* gamma = (const float*)d_in[15];
    const float* beta  = (const float*)d_in[16];

    float* out     = (float*)d_out;          // [8,256]
    float* att_out = out + 2048;             // [8,2,32,32,32]

    k_proj    <<<dim3(4, 8, 3), 256>>>(x, y, z, Vx, gx, bx, Vy, gy, by, Vz, gz, bz);
    k_attfuse <<<256, 128>>>(Vh, gh, bh, gamma, beta, out, att_out);
}

// round 11
// speedup vs baseline: 1.8317x; 1.8317x over previous
#include <cuda_runtime.h>

// ---------------- scratch (__device__ globals; no allocation allowed) ----------------
__device__ float g_hx[8*32*256];
__device__ float g_hy[8*32*256];
__device__ float g_hz[8*32*256];
__device__ float g_attraw[8*2*32768];        // pre-softmax logits [b][h][x][y][z]
__device__ float g_partmax[8*2*32];          // per (b,h,x) block max
__device__ float g_partsum[8*2*32];          // per (b,h,x) Σexp(v - localmax)
__device__ float g_part[8*32*256];           // per (b,x) logits partials

// ---------------- K1: projections  h = relu(in @ (g/||V||*V)^T + b) ----------------
__global__ void __launch_bounds__(256) k_proj(
    const float* __restrict__ xin, const float* __restrict__ yin, const float* __restrict__ zin,
    const float* __restrict__ Vx, const float* __restrict__ gx, const float* __restrict__ bx,
    const float* __restrict__ Vy, const float* __restrict__ gy, const float* __restrict__ by,
    const float* __restrict__ Vz, const float* __restrict__ gz, const float* __restrict__ bz) {
    __shared__ float sIn[32*128];
    __shared__ float sV[64*33];
    __shared__ float red[256];
    int q = blockIdx.x, b = blockIdx.y, m = blockIdx.z;
    const float* in   = (m == 0) ? xin : (m == 1) ? yin : zin;
    const float* V    = (m == 0) ? Vx  : (m == 1) ? Vy  : Vz;
    const float* gp   = (m == 0) ? gx  : (m == 1) ? gy  : gz;
    const float* bias = (m == 0) ? bx  : (m == 1) ? by  : bz;
    float* out        = (m == 0) ? g_hx : (m == 1) ? g_hy : g_hz;
    int tid = threadIdx.x;
    int k0 = q * 64;

    for (int e = tid; e < 4096; e += 256) sIn[e] = in[b * 4096 + e];
    float ss = 0.f;
    for (int i = tid; i < 32768; i += 256) { float v = V[i]; ss += v * v; }
    red[tid] = ss; __syncthreads();
    for (int s = 128; s > 0; s >>= 1) {
        if (tid < s) red[tid] += red[tid + s];
        __syncthreads();
    }
    float scale = gp[0] / sqrtf(red[0]);

    int kk = tid & 63, rg = tid >> 6, r0 = rg * 8;
    float acc[8] = {0,0,0,0,0,0,0,0};
    for (int dc = 0; dc < 128; dc += 32) {
        __syncthreads();
        for (int e = tid; e < 2048; e += 256) {
            int kr = e >> 5, d = e & 31;
            sV[kr * 33 + d] = V[(k0 + kr) * 128 + dc + d];
        }
        __syncthreads();
        for (int d = 0; d < 32; d += 4) {
            float v0 = sV[kk*33 + d],     v1 = sV[kk*33 + d + 1];
            float v2 = sV[kk*33 + d + 2], v3 = sV[kk*33 + d + 3];
            #pragma unroll
            for (int r = 0; r < 8; r++) {
                float4 iv = *(const float4*)&sIn[(r0 + r) * 128 + dc + d];
                acc[r] += iv.x * v0 + iv.y * v1 + iv.z * v2 + iv.w * v3;
            }
        }
    }
    float bb = bias[k0 + kk];
    #pragma unroll
    for (int r = 0; r < 8; r++) {
        float v = acc[r] * scale + bb;
        out[(b * 32 + r0 + r) * 256 + k0 + kk] = v > 0.f ? v : 0.f;
    }
}

// ---------------- K2: att GEMM + online-softmax partials (R7-identical) ----------------
__global__ void __launch_bounds__(128) k_att(const float* __restrict__ Vh,
                                             const float* __restrict__ ghp,
                                             const float* __restrict__ bhp) {
    __shared__ float st[32*64];
    __shared__ float sw[64*68];
    __shared__ float red[128];
    int x = blockIdx.x, b = blockIdx.y;
    int tid = threadIdx.x;
    int yg = tid >> 4, zg = tid & 15;

    float ssh = 0.f;
    for (int i = tid; i < 512; i += 128) { float v = Vh[i]; ssh += v * v; }
    red[tid] = ssh; __syncthreads();
    for (int s = 64; s > 0; s >>= 1) { if (tid < s) red[tid] += red[tid + s]; __syncthreads(); }
    float scaleH = ghp[0] / sqrtf(red[0]);

    float4 acc[4];
    acc[0] = acc[1] = acc[2] = acc[3] = make_float4(0.f, 0.f, 0.f, 0.f);
    const float* hx  = g_hx + (b * 32 + x) * 256;
    const float* hyB = g_hy + b * 8192;
    const float* hzB = g_hz + b * 8192;
    for (int c = 0; c < 4; c++) {
        int k0 = c * 64;
        __syncthreads();
        for (int e = tid; e < 2048; e += 128) {
            int kc = e & 63, y = e >> 6;
            st[y * 64 + kc] = hx[k0 + kc] * hyB[y * 256 + k0 + kc];
        }
        for (int e = tid; e < 4096; e += 128) {
            int kc = e & 63, zh = e >> 6;
            sw[kc * 68 + zh] = hzB[(zh >> 1) * 256 + k0 + kc] *
                               Vh[(zh & 1) * 256 + k0 + kc] * scaleH;
        }
        __syncthreads();
        #pragma unroll 4
        for (int kc = 0; kc < 64; kc++) {
            float4 w = *(const float4*)&sw[kc * 68 + zg * 4];
            float t0 = st[(yg*4 + 0) * 64 + kc];
            float t1 = st[(yg*4 + 1) * 64 + kc];
            float t2 = st[(yg*4 + 2) * 64 + kc];
            float t3 = st[(yg*4 + 3) * 64 + kc];
            acc[0].x += t0*w.x; acc[0].y += t0*w.y; acc[0].z += t0*w.z; acc[0].w += t0*w.w;
            acc[1].x += t1*w.x; acc[1].y += t1*w.y; acc[1].z += t1*w.z; acc[1].w += t1*w.w;
            acc[2].x += t2*w.x; acc[2].y += t2*w.y; acc[2].z += t2*w.z; acc[2].w += t2*w.w;
            acc[3].x += t3*w.x; acc[3].y += t3*w.y; acc[3].z += t3*w.z; acc[3].w += t3*w.w;
        }
    }
    float b0 = bhp[0], b1 = bhp[1];
    float m0 = -1e30f, m1 = -1e30f;
    float* r0base = g_attraw + ((b * 2 + 0) * 32 + x) * 1024;
    float* r1base = g_attraw + ((b * 2 + 1) * 32 + x) * 1024;
    int z0 = zg * 2;
    #pragma unroll
    for (int i = 0; i < 4; i++) {
        int y = yg * 4 + i;
        float4 v = acc[i];
        v.x += b0; v.y += b1; v.z += b0; v.w += b1;
        m0 = fmaxf(m0, fmaxf(v.x, v.z));
        m1 = fmaxf(m1, fmaxf(v.y, v.w));
        r0base[y * 32 + z0]     = v.x;
        r1base[y * 32 + z0]     = v.y;
        r0base[y * 32 + z0 + 1] = v.z;
        r1base[y * 32 + z0 + 1] = v.w;
    }
    __syncthreads();
    red[tid] = m0; __syncthreads();
    for (int s = 64; s > 0; s >>= 1) { if (tid < s) red[tid] = fmaxf(red[tid], red[tid + s]); __syncthreads(); }
    float M0 = red[0]; __syncthreads();
    red[tid] = m1; __syncthreads();
    for (int s = 64; s > 0; s >>= 1) { if (tid < s) red[tid] = fmaxf(red[tid], red[tid + s]); __syncthreads(); }
    float M1 = red[0]; __syncthreads();
    float s0 = 0.f, s1 = 0.f;
    #pragma unroll
    for (int i = 0; i < 4; i++) {
        float4 v = acc[i];
        s0 += expf(v.x + b0 - M0) + expf(v.z + b0 - M0);
        s1 += expf(v.y + b1 - M1) + expf(v.w + b1 - M1);
    }
    red[tid] = s0; __syncthreads();
    for (int s = 64; s > 0; s >>= 1) { if (tid < s) red[tid] += red[tid + s]; __syncthreads(); }
    float S0 = red[0]; __syncthreads();
    red[tid] = s1; __syncthreads();
    for (int s = 64; s > 0; s >>= 1) { if (tid < s) red[tid] += red[tid + s]; __syncthreads(); }
    if (tid == 0) {
        g_partmax[(b * 2 + 0) * 32 + x] = M0;
        g_partmax[(b * 2 + 1) * 32 + x] = M1;
        g_partsum[(b * 2 + 0) * 32 + x] = S0;
        g_partsum[(b * 2 + 1) * 32 + x] = red[0];
    }
}

// ---------------- K3: softmax-finalize + att_out + logit partials (conflict-free) ----------------
// grid (32 x, 8 b), 256 threads, one k each. hz staged in NATURAL [z][k] layout
// (linear copy, conflict-free reads); z-contraction register-tiled 4y x 4z:
// 4 broadcast float4 (sa) + 4 conflict-free LDS.32 (hz) per 16 FMA.
__global__ void __launch_bounds__(256) k_fuse(float* __restrict__ att_out) {
    __shared__ float sa[1024];
    __shared__ float shzN[8192];   // [z][k], natural
    __shared__ float sstat[4];
    int x = blockIdx.x, b = blockIdx.y, tid = threadIdx.x;

    // linear copy of hz for this b (coalesced float4, no transpose)
    const float* hzB = g_hz + b * 8192;
    {
        float4* s4 = (float4*)shzN;
        const float4* g4 = (const float4*)hzB;
        for (int e = tid; e < 2048; e += 256) s4[e] = g4[e];
    }
    // softmax combine: warp 0 -> h0, warp 1 -> h1
    if (tid < 64) {
        int h = tid >> 5, lane = tid & 31;
        float m = g_partmax[(b * 2 + h) * 32 + lane];
        float s = g_partsum[(b * 2 + h) * 32 + lane];
        float M = m;
        #pragma unroll
        for (int o = 16; o > 0; o >>= 1) M = fmaxf(M, __shfl_xor_sync(0xffffffffu, M, o));
        float se = s * expf(m - M);
        #pragma unroll
        for (int o = 16; o > 0; o >>= 1) se += __shfl_xor_sync(0xffffffffu, se, o);
        if (lane == 0) { sstat[h * 2] = M; sstat[h * 2 + 1] = 1.f / se; }
    }
    __syncthreads();
    float M0 = sstat[0], I0 = sstat[1], M1 = sstat[2], I1 = sstat[3];

    const float* r0 = g_attraw + ((b * 2 + 0) * 32 + x) * 1024;
    const float* r1 = g_attraw + ((b * 2 + 1) * 32 + x) * 1024;
    float* o0 = att_out + ((b * 2 + 0) * 32 + x) * 1024;
    float* o1 = att_out + ((b * 2 + 1) * 32 + x) * 1024;
    #pragma unroll
    for (int i = tid; i < 1024; i += 256) {
        float a0 = expf(r0[i] - M0) * I0;
        float a1 = expf(r1[i] - M1) * I1;
        o0[i] = a0;
        o1[i] = a1;
        sa[i] = a0 + a1;
    }
    __syncthreads();

    // logit partial for k = tid
    float sxk = g_hx[(b * 32 + x) * 256 + tid];
    const float* hyB = g_hy + b * 8192;
    const float4* sa4 = (const float4*)sa;
    float p = 0.f;
    #pragma unroll
    for (int y0 = 0; y0 < 32; y0 += 4) {
        float s0 = 0.f, s1 = 0.f, s2 = 0.f, s3 = 0.f;
        #pragma unroll
        for (int zc = 0; zc < 8; zc++) {
            float4 a0 = sa4[(y0 + 0) * 8 + zc];      // broadcast
            float4 a1 = sa4[(y0 + 1) * 8 + zc];
            float4 a2 = sa4[(y0 + 2) * 8 + zc];
            float4 a3 = sa4[(y0 + 3) * 8 + zc];
            float h0 = shzN[(zc * 4 + 0) * 256 + tid];   // conflict-free
            float h1 = shzN[(zc * 4 + 1) * 256 + tid];
            float h2 = shzN[(zc * 4 + 2) * 256 + tid];
            float h3 = shzN[(zc * 4 + 3) * 256 + tid];
            s0 += a0.x*h0 + a0.y*h1 + a0.z*h2 + a0.w*h3;
            s1 += a1.x*h0 + a1.y*h1 + a1.z*h2 + a1.w*h3;
            s2 += a2.x*h0 + a2.y*h1 + a2.z*h2 + a2.w*h3;
            s3 += a3.x*h0 + a3.y*h1 + a3.z*h2 + a3.w*h3;
        }
        float t0 = hyB[(y0 + 0) * 256 + tid];
        float t1 = hyB[(y0 + 1) * 256 + tid];
        float t2 = hyB[(y0 + 2) * 256 + tid];
        float t3 = hyB[(y0 + 3) * 256 + tid];
        p += sxk * (t0 * s0 + t1 * s1 + t2 * s2 + t3 * s3);
    }
    g_part[(b * 32 + x) * 256 + tid] = p;
}

// ---------------- K4: reduce partials + BatchNorm — one warp per k (R7-identical) ----------------
__global__ void __launch_bounds__(256) k_bn(const float* __restrict__ gamma,
                                            const float* __restrict__ beta,
                                            float* __restrict__ outp) {
    int warp = threadIdx.x >> 5, lane = threadIdx.x & 31;
    int k = blockIdx.x * 8 + warp;
    float l[8];
    #pragma unroll
    for (int b = 0; b < 8; b++) l[b] = g_part[(b * 32 + lane) * 256 + k];
    #pragma unroll
    for (int b = 0; b < 8; b++) {
        float v = l[b];
        #pragma unroll
        for (int o = 16; o > 0; o >>= 1) v += __shfl_xor_sync(0xffffffffu, v, o);
        l[b] = v;
    }
    float mean = 0.f;
    #pragma unroll
    for (int b = 0; b < 8; b++) mean += l[b];
    mean *= 0.125f;
    float var = 0.f;
    #pragma unroll
    for (int b = 0; b < 8; b++) { float d = l[b] - mean; var += d * d; }
    var *= 0.125f;
    float sc = gamma[k] / sqrtf(var + 1e-5f);
    float bt = beta[k];
    if (lane < 8) outp[lane * 256 + k] = (l[lane] - mean) * sc + bt;
}

// ---------------- launch ----------------
extern "C" void kernel_launch(void* const* d_in, const int* in_sizes, int n_in,
                              void* d_out, int out_size) {
    const float* x     = (const float*)d_in[0];
    const float* y     = (const float*)d_in[1];
    const float* z     = (const float*)d_in[2];
    const float* Vx    = (const float*)d_in[3];
    const float* gx    = (const float*)d_in[4];
    const float* bx    = (const float*)d_in[5];
    const float* Vy    = (const float*)d_in[6];
    const float* gy    = (const float*)d_in[7];
    const float* by    = (const float*)d_in[8];
    const float* Vz    = (const float*)d_in[9];
    const float* gz    = (const float*)d_in[10];
    const float* bz    = (const float*)d_in[11];
    const float* Vh    = (const float*)d_in[12];
    const float* gh    = (const float*)d_in[13];
    const float* bh    = (const float*)d_in[14];
    const float* gamma = (const float*)d_in[15];
    const float* beta  = (const float*)d_in[16];

    float* out     = (float*)d_out;          // [8,256]
    float* att_out = out + 2048;             // [8,2,32,32,32]

    k_proj <<<dim3(4, 8, 3), 256>>>(x, y, z, Vx, gx, bx, Vy, gy, by, Vz, gz, bz);
    k_att  <<<dim3(32, 8), 128>>>(Vh, gh, bh);
    k_fuse <<<dim3(32, 8), 256>>>(att_out);
    k_bn   <<<32, 256>>>(gamma, beta, out);
}